// round 4
// baseline (speedup 1.0000x reference)
#include <cuda_runtime.h>
#include <cuda_bf16.h>
#include <math.h>

// Problem constants
#define Bc 8
#define Ec 1024
#define Dc 256
#define Hc 16
#define HDc 16
#define Tc (Bc*Ec)          // 8192 tokens

// ---------------- scratch (device globals: allocation-free) ----------------
__device__ float g_q [Tc*Dc];
__device__ float g_k [Tc*Dc];
__device__ float g_v [Tc*Dc];
__device__ float g_ao[Tc*Dc];
__device__ float g_x1[Tc*Dc];
__device__ float g_ff[Tc*4*Dc];
__device__ float g_tmp[Tc*Dc];

// ---------------- fast exp (FMA pipe only, no MUFU) ----------------
__device__ __forceinline__ float fexp(float x) {
    // valid for x <= ~0 (softmax args); clamp avoids denormal/underflow issues
    x = fmaxf(x, -80.0f);
    float t = x * 1.4426950408889634f;          // x * log2(e)
    float z = t + 12582912.0f;                  // round-to-nearest via magic number
    float r = t - (z - 12582912.0f);            // frac in [-0.5, 0.5]
    int ebits = (__float_as_int(z) << 23) + 0x3f800000;  // 2^i bits
    float p = 1.3333558146e-3f;
    p = fmaf(p, r, 9.6181291076e-3f);
    p = fmaf(p, r, 5.5504108664e-2f);
    p = fmaf(p, r, 2.4022650696e-1f);
    p = fmaf(p, r, 6.9314718056e-1f);
    p = fmaf(p, r, 1.0f);
    return __int_as_float(ebits) * p;
}

__device__ __forceinline__ float gelu_exact(float v) {
    return 0.5f * v * (1.0f + erff(v * 0.7071067811865476f));
}

// ---------------- tiled fp32 GEMM: C = A[M,K] @ W[K,N] + bias, optional GELU ----------------
#define BM 64
#define BN 64
#define BKK 16

__global__ __launch_bounds__(256) void gemm_kernel(
    const float* __restrict__ A, const float* __restrict__ W,
    const float* __restrict__ bias, float* __restrict__ C,
    int M, int N, int K, int act)
{
    __shared__ float AsT[BKK][BM + 4];   // [k][m], padded
    __shared__ float Ws [BKK][BN];       // [k][n]
    const int tid = threadIdx.x;
    const int tx = tid & 15, ty = tid >> 4;
    const int m0 = blockIdx.y * BM, n0 = blockIdx.x * BN;

    float acc[4][4] = {};

    for (int k0 = 0; k0 < K; k0 += BKK) {
        // load A tile (64 rows x 16 cols) as float4, store transposed
        {
            int r = tid >> 2, c4 = tid & 3;
            float4 av = *(const float4*)(A + (size_t)(m0 + r) * K + k0 + c4 * 4);
            AsT[c4 * 4 + 0][r] = av.x;
            AsT[c4 * 4 + 1][r] = av.y;
            AsT[c4 * 4 + 2][r] = av.z;
            AsT[c4 * 4 + 3][r] = av.w;
        }
        // load W tile (16 rows x 64 cols) as float4
        {
            int r = tid >> 4, c4 = tid & 15;
            *(float4*)&Ws[r][c4 * 4] =
                *(const float4*)(W + (size_t)(k0 + r) * N + n0 + c4 * 4);
        }
        __syncthreads();
        #pragma unroll
        for (int k = 0; k < BKK; k++) {
            float4 a = *(const float4*)&AsT[k][ty * 4];
            float4 w = *(const float4*)&Ws[k][tx * 4];
            acc[0][0] = fmaf(a.x, w.x, acc[0][0]); acc[0][1] = fmaf(a.x, w.y, acc[0][1]);
            acc[0][2] = fmaf(a.x, w.z, acc[0][2]); acc[0][3] = fmaf(a.x, w.w, acc[0][3]);
            acc[1][0] = fmaf(a.y, w.x, acc[1][0]); acc[1][1] = fmaf(a.y, w.y, acc[1][1]);
            acc[1][2] = fmaf(a.y, w.z, acc[1][2]); acc[1][3] = fmaf(a.y, w.w, acc[1][3]);
            acc[2][0] = fmaf(a.z, w.x, acc[2][0]); acc[2][1] = fmaf(a.z, w.y, acc[2][1]);
            acc[2][2] = fmaf(a.z, w.z, acc[2][2]); acc[2][3] = fmaf(a.z, w.w, acc[2][3]);
            acc[3][0] = fmaf(a.w, w.x, acc[3][0]); acc[3][1] = fmaf(a.w, w.y, acc[3][1]);
            acc[3][2] = fmaf(a.w, w.z, acc[3][2]); acc[3][3] = fmaf(a.w, w.w, acc[3][3]);
        }
        __syncthreads();
    }

    // epilogue: bias (+ GELU), vectorized store
    float4 bv = *(const float4*)(bias + n0 + tx * 4);
    #pragma unroll
    for (int i = 0; i < 4; i++) {
        float4 o;
        o.x = acc[i][0] + bv.x;
        o.y = acc[i][1] + bv.y;
        o.z = acc[i][2] + bv.z;
        o.w = acc[i][3] + bv.w;
        if (act) {
            o.x = gelu_exact(o.x); o.y = gelu_exact(o.y);
            o.z = gelu_exact(o.z); o.w = gelu_exact(o.w);
        }
        *(float4*)(C + (size_t)(m0 + ty * 4 + i) * N + n0 + tx * 4) = o;
    }
}

// ---------------- attention: flash-style, all 16 heads per (b, q-tile) block ----------------
#define QT 32     // queries per block
#define KT 16     // keys per tile

__global__ __launch_bounds__(512, 2) void attn_kernel(
    const float* __restrict__ Q, const float* __restrict__ Km, const float* __restrict__ V,
    const int* __restrict__ sb, const unsigned char* __restrict__ mask,
    const float* __restrict__ bias_emb, float* __restrict__ O)
{
    __shared__ float sK[KT][Dc];
    __shared__ float sV[KT][Dc];
    __shared__ int   sSB[QT][KT + 1];
    __shared__ float sBE[Hc * 8];      // [h*8 + biasIdx]
    __shared__ float sM[KT];           // 0 or -1e30

    const int b   = blockIdx.y;
    const int q0  = blockIdx.x * QT;
    const int tid = threadIdx.x;
    const int h   = tid >> 5;          // warp = head (warp-uniform)
    const int q   = tid & 31;          // lane = query within tile

    // one-time: bias embedding to smem, layout [h][idx] padded to 8
    if (tid < 6 * Hc) {
        int idx = tid / Hc, hh = tid % Hc;
        sBE[hh * 8 + idx] = bias_emb[tid];
    }

    // q row for this (q, h), scale 1/sqrt(HD)=0.25 folded into q
    float qr[HDc];
    {
        const float4* qp = (const float4*)(Q + ((size_t)(b * Ec + q0 + q)) * Dc + h * HDc);
        #pragma unroll
        for (int i = 0; i < 4; i++) {
            float4 t = qp[i];
            qr[i*4+0] = t.x * 0.25f; qr[i*4+1] = t.y * 0.25f;
            qr[i*4+2] = t.z * 0.25f; qr[i*4+3] = t.w * 0.25f;
        }
    }

    float m = -1e30f, l = 0.0f;
    float acc[HDc] = {};

    for (int k0 = 0; k0 < Ec; k0 += KT) {
        __syncthreads();    // protect smem from previous iteration's readers
        // cooperative loads: K,V tiles (KT*Dc = 4096 floats = 1024 float4 each)
        {
            const float4* Kg = (const float4*)(Km + ((size_t)(b * Ec + k0)) * Dc);
            const float4* Vg = (const float4*)(V  + ((size_t)(b * Ec + k0)) * Dc);
            float4* sK4 = (float4*)sK;
            float4* sV4 = (float4*)sV;
            sK4[tid]       = Kg[tid];
            sK4[tid + 512] = Kg[tid + 512];
            sV4[tid]       = Vg[tid];
            sV4[tid + 512] = Vg[tid + 512];
        }
        // struct bias tile: QT x KT ints (one per thread)
        {
            int r = tid >> 4, c = tid & 15;
            sSB[r][c] = sb[(size_t)b * Ec * Ec + (size_t)(q0 + r) * Ec + k0 + c];
        }
        if (tid < KT) sM[tid] = mask[b * Ec + k0 + tid] ? -1e30f : 0.0f;
        __syncthreads();

        // scores for this (q,h) against KT keys
        float sc[KT];
        float mt = m;
        #pragma unroll
        for (int kk = 0; kk < KT; kk++) {
            const float4* kv = (const float4*)&sK[kk][h * HDc];
            float4 k0v = kv[0], k1v = kv[1], k2v = kv[2], k3v = kv[3];
            float s = qr[0] * k0v.x;
            s = fmaf(qr[1],  k0v.y, s); s = fmaf(qr[2],  k0v.z, s); s = fmaf(qr[3],  k0v.w, s);
            s = fmaf(qr[4],  k1v.x, s); s = fmaf(qr[5],  k1v.y, s); s = fmaf(qr[6],  k1v.z, s); s = fmaf(qr[7],  k1v.w, s);
            s = fmaf(qr[8],  k2v.x, s); s = fmaf(qr[9],  k2v.y, s); s = fmaf(qr[10], k2v.z, s); s = fmaf(qr[11], k2v.w, s);
            s = fmaf(qr[12], k3v.x, s); s = fmaf(qr[13], k3v.y, s); s = fmaf(qr[14], k3v.z, s); s = fmaf(qr[15], k3v.w, s);
            int bi = sSB[q][kk];
            s += sBE[h * 8 + bi] + sM[kk];
            sc[kk] = s;
            mt = fmaxf(mt, s);
        }
        // online softmax update
        float scale = fexp(m - mt);
        m = mt;
        l *= scale;
        #pragma unroll
        for (int i = 0; i < HDc; i++) acc[i] *= scale;
        #pragma unroll
        for (int kk = 0; kk < KT; kk++) {
            float p = fexp(sc[kk] - mt);
            l += p;
            const float4* vv = (const float4*)&sV[kk][h * HDc];
            float4 v0 = vv[0], v1 = vv[1], v2 = vv[2], v3 = vv[3];
            acc[0]  = fmaf(p, v0.x, acc[0]);  acc[1]  = fmaf(p, v0.y, acc[1]);
            acc[2]  = fmaf(p, v0.z, acc[2]);  acc[3]  = fmaf(p, v0.w, acc[3]);
            acc[4]  = fmaf(p, v1.x, acc[4]);  acc[5]  = fmaf(p, v1.y, acc[5]);
            acc[6]  = fmaf(p, v1.z, acc[6]);  acc[7]  = fmaf(p, v1.w, acc[7]);
            acc[8]  = fmaf(p, v2.x, acc[8]);  acc[9]  = fmaf(p, v2.y, acc[9]);
            acc[10] = fmaf(p, v2.z, acc[10]); acc[11] = fmaf(p, v2.w, acc[11]);
            acc[12] = fmaf(p, v3.x, acc[12]); acc[13] = fmaf(p, v3.y, acc[13]);
            acc[14] = fmaf(p, v3.z, acc[14]); acc[15] = fmaf(p, v3.w, acc[15]);
        }
    }

    float inv = 1.0f / l;
    float4* op = (float4*)(O + ((size_t)(b * Ec + q0 + q)) * Dc + h * HDc);
    #pragma unroll
    for (int i = 0; i < 4; i++) {
        float4 o;
        o.x = acc[i*4+0] * inv; o.y = acc[i*4+1] * inv;
        o.z = acc[i*4+2] * inv; o.w = acc[i*4+3] * inv;
        op[i] = o;
    }
}

// ---------------- residual add + layernorm: out = LN(x + y) * g + b ----------------
__global__ __launch_bounds__(256) void add_ln_kernel(
    const float* __restrict__ x, const float* __restrict__ y,
    const float* __restrict__ g, const float* __restrict__ b,
    float* __restrict__ out)
{
    const int row  = blockIdx.x * 8 + (threadIdx.x >> 5);
    const int lane = threadIdx.x & 31;
    const float* xr = x + (size_t)row * Dc;
    const float* yr = y + (size_t)row * Dc;

    float v[8];
    float s = 0.0f, s2 = 0.0f;
    #pragma unroll
    for (int i = 0; i < 8; i++) {
        float t = xr[i * 32 + lane] + yr[i * 32 + lane];
        v[i] = t;
        s += t;
        s2 = fmaf(t, t, s2);
    }
    #pragma unroll
    for (int o = 16; o > 0; o >>= 1) {
        s  += __shfl_xor_sync(0xFFFFFFFFu, s,  o);
        s2 += __shfl_xor_sync(0xFFFFFFFFu, s2, o);
    }
    float mu  = s * (1.0f / 256.0f);
    float var = s2 * (1.0f / 256.0f) - mu * mu;
    float r   = rsqrtf(var + 1e-5f);
    #pragma unroll
    for (int i = 0; i < 8; i++) {
        int c = i * 32 + lane;
        out[(size_t)row * Dc + c] = (v[i] - mu) * r * g[c] + b[c];
    }
}

// ---------------- launch ----------------
extern "C" void kernel_launch(void* const* d_in, const int* in_sizes, int n_in,
                              void* d_out, int out_size)
{
    const float* x    = (const float*)d_in[0];
    const int*   sb   = (const int*)d_in[1];
    const unsigned char* mask = (const unsigned char*)d_in[2];
    const float* Wq = (const float*)d_in[3];  const float* bq = (const float*)d_in[4];
    const float* Wk = (const float*)d_in[5];  const float* bk = (const float*)d_in[6];
    const float* Wv = (const float*)d_in[7];  const float* bv = (const float*)d_in[8];
    const float* Wo = (const float*)d_in[9];  const float* bo = (const float*)d_in[10];
    const float* be = (const float*)d_in[11];
    const float* g1 = (const float*)d_in[12]; const float* b1 = (const float*)d_in[13];
    const float* Wf1 = (const float*)d_in[14]; const float* bf1 = (const float*)d_in[15];
    const float* Wf2 = (const float*)d_in[16]; const float* bf2 = (const float*)d_in[17];
    const float* g2 = (const float*)d_in[18]; const float* b2 = (const float*)d_in[19];
    float* out = (float*)d_out;

    float *q, *k, *v, *ao, *x1, *ff, *tmp;
    cudaGetSymbolAddress((void**)&q,  g_q);
    cudaGetSymbolAddress((void**)&k,  g_k);
    cudaGetSymbolAddress((void**)&v,  g_v);
    cudaGetSymbolAddress((void**)&ao, g_ao);
    cudaGetSymbolAddress((void**)&x1, g_x1);
    cudaGetSymbolAddress((void**)&ff, g_ff);
    cudaGetSymbolAddress((void**)&tmp, g_tmp);

    dim3 gQKV(Dc / BN, Tc / BM);           // (4, 128)
    dim3 gFF1(4 * Dc / BN, Tc / BM);       // (16, 128)

    gemm_kernel<<<gQKV, 256>>>(x, Wq, bq, q, Tc, Dc, Dc, 0);
    gemm_kernel<<<gQKV, 256>>>(x, Wk, bk, k, Tc, Dc, Dc, 0);
    gemm_kernel<<<gQKV, 256>>>(x, Wv, bv, v, Tc, Dc, Dc, 0);

    attn_kernel<<<dim3(Ec / QT, Bc), 512>>>(q, k, v, sb, mask, be, ao);

    gemm_kernel<<<gQKV, 256>>>(ao, Wo, bo, tmp, Tc, Dc, Dc, 0);
    add_ln_kernel<<<Tc / 8, 256>>>(x, tmp, g1, b1, x1);

    gemm_kernel<<<gFF1, 256>>>(x1, Wf1, bf1, ff, Tc, 4 * Dc, Dc, 1);
    gemm_kernel<<<gQKV, 256>>>(ff, Wf2, bf2, tmp, Tc, Dc, 4 * Dc, 0);
    add_ln_kernel<<<Tc / 8, 256>>>(x1, tmp, g2, b2, out);
}